// round 16
// baseline (speedup 1.0000x reference)
#include <cuda_runtime.h>
#include <cuda_bf16.h>
#include <math.h>
#include <stdint.h>

// ---------------- problem constants ----------------
#define CC 384
#define WS 7
#define NT 49
#define HEADS 12
#define HD 32
#define NWIN 1024
#define MROWS (NWIN * NT)   // 50176
#define C4 (CC / 4)

#if defined(__CUDA_ARCH_FEAT_SM103_ALL) || defined(__CUDA_ARCH_FEAT_SM100_ALL) || defined(__CUDA_ARCH_FEAT_SM101_ALL)
#define TC_OK 1
#else
#define TC_OK 0
#endif

// ---------------- scratch (device globals) ----------------
__device__ float g_xw[MROWS * CC];                 // residual stream (fp32)
__device__ __nv_bfloat16 g_h[MROWS * CC];          // LN output (bf16)
__device__ float g_qkv[MROWS * 3 * CC];            // qkv (fp32, feeds attention)
__device__ __nv_bfloat16 g_o[MROWS * CC];          // attention output (bf16)
__device__ __nv_bfloat16 g_hidden[MROWS * 4 * CC]; // gelu output (bf16)
#define WT_LAYER 1769472
__device__ __nv_bfloat16 g_wT[2 * WT_LAYER];       // transposed weights (bf16)

#define OFF_QKV  0
#define OFF_PROJ 442368
#define OFF_W1   589824
#define OFF_W2   1179648

// ---------------- small helpers ----------------
__device__ __forceinline__ uint32_t smem_u32(const void* p) {
    uint32_t a;
    asm("{ .reg .u64 t; cvta.to.shared.u64 t, %1; cvt.u32.u64 %0, t; }" : "=r"(a) : "l"(p));
    return a;
}
__device__ __forceinline__ void cp16(uint32_t dst, const void* src) {
    asm volatile("cp.async.cg.shared.global [%0], [%1], 16;" :: "r"(dst), "l"(src));
}
// windowed row r <-> image row perm(r)
__device__ __forceinline__ int perm_row(int r) {
    int w = r / NT, tt = r - w * NT;
    int b = w >> 6, wrem = w & 63, wy = wrem >> 3, wx = wrem & 7;
    int ty = tt / WS, tx = tt - ty * WS;
    return (b * 56 + wy * WS + ty) * 56 + wx * WS + tx;
}

// SW32 swizzle (32B rows): bit[4] ^= bit[7]
#define SWZ32(o) ((o) ^ (((o) >> 3) & 0x10))
// SW32 K-major smem descriptor: layout=6, version=1, SBO=16 (256B atom), LBO=1
#define DESC_SW32 ((6ull << 61) | (1ull << 46) | (16ull << 32) | (1ull << 16))
// idesc kind::f16 bf16: dtype=F32(1<<4), atype=BF16(1<<7), btype=BF16(1<<10),
// N=128 (16<<17), M=128 (8<<24)
#define IDESC_BF16 0x08200490u

#define STAGE_BYTES 8192           // A 4KB + B 4KB  (K-chunk = 16 bf16 per 32B row)
#define NSTAGE 6

#if TC_OK
__device__ __forceinline__ void mbar_wait(uint32_t mb, int parity) {
    asm volatile(
        "{\n\t.reg .pred P;\n"
        "W%=:\n\t"
        "mbarrier.try_wait.parity.acquire.cta.shared::cta.b64 P, [%0], %1, 0x989680;\n\t"
        "@P bra D%=;\n\t"
        "bra W%=;\n"
        "D%=:\n\t}"
        :: "r"(mb), "r"(parity) : "memory");
}
__device__ __forceinline__ void mma_bf16_ss(uint32_t d, uint64_t a, uint64_t b,
                                            uint32_t idesc, uint32_t en) {
    asm volatile(
        "{\n\t.reg .pred p;\n\t"
        "setp.ne.u32 p, %4, 0;\n\t"
        "tcgen05.mma.cta_group::1.kind::f16 [%0], %1, %2, %3, p;\n\t}"
        :: "r"(d), "l"(a), "l"(b), "r"(idesc), "r"(en) : "memory");
}
#define LDTM_X16(r, a) \
    asm volatile("tcgen05.ld.sync.aligned.32x32b.x16.b32 " \
        "{%0,%1,%2,%3,%4,%5,%6,%7,%8,%9,%10,%11,%12,%13,%14,%15}, [%16];" \
        : "=r"((r)[0]),"=r"((r)[1]),"=r"((r)[2]),"=r"((r)[3]), \
          "=r"((r)[4]),"=r"((r)[5]),"=r"((r)[6]),"=r"((r)[7]), \
          "=r"((r)[8]),"=r"((r)[9]),"=r"((r)[10]),"=r"((r)[11]), \
          "=r"((r)[12]),"=r"((r)[13]),"=r"((r)[14]),"=r"((r)[15]) \
        : "r"(a))
#endif

// ---------------- fused weight transpose -> bf16 K-major ----------------
__global__ void transpose_all(const float* __restrict__ qkv_w,
                              const float* __restrict__ proj_w,
                              const float* __restrict__ w1,
                              const float* __restrict__ w2,
                              __nv_bfloat16* __restrict__ wT) {
    __shared__ float t[32][33];
    int id = blockIdx.x, l = blockIdx.y;
    const float* src; size_t doff; int K, N, tn;
    if (id < 432)       { src = qkv_w  + (size_t)l*384*1152; doff = OFF_QKV;  K = 384;  N = 1152; tn = 36; }
    else if (id < 576)  { id -= 432; src = proj_w + (size_t)l*384*384;  doff = OFF_PROJ; K = 384;  N = 384;  tn = 12; }
    else if (id < 1152) { id -= 576; src = w1     + (size_t)l*384*1536; doff = OFF_W1;   K = 384;  N = 1536; tn = 48; }
    else                { id -= 1152; src = w2    + (size_t)l*1536*384; doff = OFF_W2;   K = 1536; N = 384;  tn = 12; }
    __nv_bfloat16* dst = wT + (size_t)l * WT_LAYER + doff;
    int k0 = (id / tn) * 32, n0 = (id % tn) * 32;
    int tx = threadIdx.x, ty = threadIdx.y;
    #pragma unroll
    for (int i = 0; i < 32; i += 8)
        t[ty + i][tx] = src[(size_t)(k0 + ty + i) * N + n0 + tx];
    __syncthreads();
    #pragma unroll
    for (int i = 0; i < 32; i += 8)
        dst[(size_t)(n0 + ty + i) * K + k0 + tx] = __float2bfloat16(t[tx][ty + i]);
}

// ---------------- layernorm: fp32 in -> bf16 out ----------------
template <int PERM>
__global__ __launch_bounds__(256) void ln_kernel(const float* __restrict__ xin,
                                                 const float* __restrict__ sc,
                                                 const float* __restrict__ bi,
                                                 __nv_bfloat16* __restrict__ outp) {
    int warp = threadIdx.x >> 5, lane = threadIdx.x & 31;
    int row = blockIdx.x * 8 + warp;
    int srow = PERM ? perm_row(row) : row;
    const float4* xr = (const float4*)(xin + (size_t)srow * CC);
    float4 v0 = xr[lane], v1 = xr[lane + 32], v2 = xr[lane + 64];
    float s = v0.x + v0.y + v0.z + v0.w + v1.x + v1.y + v1.z + v1.w + v2.x + v2.y + v2.z + v2.w;
    float s2 = v0.x*v0.x + v0.y*v0.y + v0.z*v0.z + v0.w*v0.w
             + v1.x*v1.x + v1.y*v1.y + v1.z*v1.z + v1.w*v1.w
             + v2.x*v2.x + v2.y*v2.y + v2.z*v2.z + v2.w*v2.w;
    #pragma unroll
    for (int o = 16; o; o >>= 1) {
        s  += __shfl_xor_sync(0xffffffffu, s, o);
        s2 += __shfl_xor_sync(0xffffffffu, s2, o);
    }
    float mu = s * (1.0f / CC);
    float var = s2 * (1.0f / CC) - mu * mu;
    float rstd = rsqrtf(var + 1e-6f);
    const float4* s4 = (const float4*)sc;
    const float4* b4 = (const float4*)bi;
    __nv_bfloat16* orow = outp + (size_t)row * CC;
    #pragma unroll
    for (int c = 0; c < 3; c++) {
        float4 v = c == 0 ? v0 : (c == 1 ? v1 : v2);
        float4 g = s4[lane + c * 32], bb = b4[lane + c * 32];
        float rx = (v.x - mu) * rstd * g.x + bb.x;
        float ry = (v.y - mu) * rstd * g.y + bb.y;
        float rz = (v.z - mu) * rstd * g.z + bb.z;
        float rw = (v.w - mu) * rstd * g.w + bb.w;
        __nv_bfloat162 p0 = __floats2bfloat162_rn(rx, ry);
        __nv_bfloat162 p1 = __floats2bfloat162_rn(rz, rw);
        uint2 pk;
        pk.x = *(uint32_t*)&p0;
        pk.y = *(uint32_t*)&p1;
        *(uint2*)(orow + (lane + c * 32) * 4) = pk;
    }
}

// ---------------- gelu ----------------
__device__ __forceinline__ float gelu_tanh(float x) {
    float x3 = x * x * x;
    return 0.5f * x * (1.0f + tanhf(0.7978845608028654f * (x + 0.044715f * x3)));
}

// ---------------- GEMM: C[M,N] = A[M,K] * B[N,K]^T ; bf16 in, fp32 acc ----------------
// CTA tile 128x128, K-stage = 16 bf16 (SW32 32B rows): 6-stage ring = 48KB -> 4 CTA/SM.
// Deeper ring at constant smem: each buffer has 6 stage-periods to complete the
// commit->done->load->full->MMA round trip (vs 3 before).
// 288 threads: warps 0-7 load (256 threads x 2 chunks), warp 8 lane 0 issues MMAs.
// EPI: 0 qkv fp32 | 2 gelu+bias->bf16 | 3 acc+bias+res | 4 acc+res
//      5 acc+res(perm rows) | 6 acc+bias+res store-permuted
template <int EPI>
__global__ __launch_bounds__(288, 4) void tc_gemm(const __nv_bfloat16* __restrict__ A,
                                                  const __nv_bfloat16* __restrict__ B,
                                                  const float* __restrict__ bias,
                                                  const float* __restrict__ res,
                                                  float* __restrict__ C,
                                                  int K, int N) {
    extern __shared__ char smem[];
#if TC_OK
    uint32_t raw = smem_u32(smem);
    uint32_t base = (raw + 1023) & ~1023u;
    uint32_t ctrl = base + NSTAGE * STAGE_BYTES;
    uint32_t fullb[NSTAGE], doneb[NSTAGE];
    #pragma unroll
    for (int i = 0; i < NSTAGE; i++) {
        fullb[i] = ctrl + i * 8;
        doneb[i] = ctrl + NSTAGE * 8 + i * 8;
    }
    uint32_t tptr = ctrl + 2 * NSTAGE * 8;
    int tid = threadIdx.x, wid = tid >> 5, lane = tid & 31;
    int m0 = blockIdx.y << 7;
    int n0 = blockIdx.x << 7;
    int S = K >> 4;   // K stages of 16 (24 or 96)

    auto load_stage = [&](int s) {   // tid < 256 only
        int b = s % NSTAGE;
        uint32_t st = base + b * STAGE_BYTES;
        int k0 = s << 4;
        #pragma unroll
        for (int i = 0; i < 2; i++) {
            int g = (i << 8) + tid;            // 0..511 16B-chunks
            int tile = g >> 8;                 // 0 = A, 1 = B
            int w = g & 255;
            int row = w >> 1;
            int cb  = (w & 1) << 4;            // byte col in 32B row
            uint32_t dst = st + (tile << 12) + SWZ32(row * 32 + cb);
            const __nv_bfloat16* src = (tile == 0)
                ? A + (size_t)(m0 + row) * K + k0 + (cb >> 1)
                : B + (size_t)(n0 + row) * K + k0 + (cb >> 1);
            cp16(dst, src);
        }
        asm volatile("cp.async.mbarrier.arrive.noinc.shared::cta.b64 [%0];"
                     :: "r"(fullb[b]) : "memory");
    };

    if (wid == 0) {
        asm volatile("tcgen05.alloc.cta_group::1.sync.aligned.shared::cta.b32 [%0], %1;"
                     :: "r"(tptr), "r"(128) : "memory");
        asm volatile("tcgen05.relinquish_alloc_permit.cta_group::1.sync.aligned;");
    }
    if (tid == 0) {
        #pragma unroll
        for (int i = 0; i < NSTAGE; i++) {
            asm volatile("mbarrier.init.shared.b64 [%0], 256;" :: "r"(fullb[i]) : "memory");
            asm volatile("mbarrier.init.shared.b64 [%0], 1;"   :: "r"(doneb[i]) : "memory");
        }
    }
    __syncthreads();
    uint32_t tmem;
    asm volatile("ld.shared.b32 %0, [%1];" : "=r"(tmem) : "r"(tptr));

    if (tid < 256) {
        #pragma unroll
        for (int s = 0; s < NSTAGE; s++) load_stage(s);
    }

    if (wid == 8) {
        // ---- MMA issuer: gated only by full[b] ----
        if (lane == 0) {
            int fph[NSTAGE] = {0, 0, 0, 0, 0, 0};
            for (int s = 0; s < S; s++) {
                int b = s % NSTAGE;
                mbar_wait(fullb[b], fph[b]); fph[b] ^= 1;
                asm volatile("fence.proxy.async.shared::cta;" ::: "memory");
                uint32_t st = base + b * STAGE_BYTES;
                uint64_t ad = DESC_SW32 | ((uint64_t)(st >> 4) & 0x3FFF);
                uint64_t bd = DESC_SW32 | ((uint64_t)((st + 4096) >> 4) & 0x3FFF);
                mma_bf16_ss(tmem, ad, bd, IDESC_BF16, s != 0);
                asm volatile("tcgen05.commit.cta_group::1.mbarrier::arrive::one.shared::cluster.b64 [%0];"
                             :: "r"(doneb[b]) : "memory");
            }
        }
    } else {
        // ---- loaders: gated only by done[b] (buffer recycling) ----
        int dph[NSTAGE] = {0, 0, 0, 0, 0, 0};
        for (int s = NSTAGE; s < S; s++) {
            int b = s % NSTAGE;
            mbar_wait(doneb[b], dph[b]); dph[b] ^= 1;
            load_stage(s);
        }
        int bl = (S - 1) % NSTAGE;
        mbar_wait(doneb[bl], dph[bl]);
    }
    __syncthreads();

    asm volatile("tcgen05.fence::after_thread_sync;" ::: "memory");
    if (wid < 8) {
        int row = m0 + ((wid & 3) << 5) + lane;
        int rrow_i = (EPI == 5) ? perm_row(row) : row;   // residual source row
        int srow_i = (EPI == 6) ? perm_row(row) : row;   // store destination row
        int colbase = (wid >> 2) << 6;
        uint32_t toff = tmem + ((uint32_t)(wid & 3) << 21);
        #pragma unroll
        for (int g = 0; g < 4; g++) {
            int col = colbase + g * 16;
            uint32_t r[16];
            LDTM_X16(r, toff + col);
            asm volatile("tcgen05.wait::ld.sync.aligned;" ::: "memory");
            float* crow = C + (size_t)srow_i * N + n0 + col;
            __nv_bfloat16* crow16 = (__nv_bfloat16*)C + (size_t)srow_i * N + n0 + col;
            const float4* rrow = (EPI >= 3)
                ? (const float4*)(res + (size_t)rrow_i * N + n0 + col) : nullptr;
            const float4* b4 = (EPI == 2 || EPI == 3 || EPI == 6)
                ? (const float4*)(bias + n0 + col) : nullptr;
            #pragma unroll
            for (int j = 0; j < 16; j += 4) {
                float4 v;
                v.x = __uint_as_float(r[j + 0]);
                v.y = __uint_as_float(r[j + 1]);
                v.z = __uint_as_float(r[j + 2]);
                v.w = __uint_as_float(r[j + 3]);
                if (EPI == 2 || EPI == 3 || EPI == 6) {
                    float4 bb = b4[j >> 2];
                    v.x += bb.x; v.y += bb.y; v.z += bb.z; v.w += bb.w;
                }
                if (EPI == 2) {
                    v.x = gelu_tanh(v.x); v.y = gelu_tanh(v.y);
                    v.z = gelu_tanh(v.z); v.w = gelu_tanh(v.w);
                    __nv_bfloat162 p0 = __floats2bfloat162_rn(v.x, v.y);
                    __nv_bfloat162 p1 = __floats2bfloat162_rn(v.z, v.w);
                    *(__nv_bfloat162*)(crow16 + j)     = p0;
                    *(__nv_bfloat162*)(crow16 + j + 2) = p1;
                } else {
                    if (EPI >= 3) {
                        float4 rr = rrow[j >> 2];
                        v.x += rr.x; v.y += rr.y; v.z += rr.z; v.w += rr.w;
                    }
                    *(float4*)(crow + j) = v;
                }
            }
        }
    }
    __syncthreads();
    if (wid == 0)
        asm volatile("tcgen05.dealloc.cta_group::1.sync.aligned.b32 %0, %1;"
                     :: "r"(tmem), "r"(128));
#else
    // ---------- SIMT fallback (plain sm_103 target; never selected at runtime) ----------
    (void)smem;
    int tid = threadIdx.x;
    int m0 = blockIdx.y << 7;
    int n0 = blockIdx.x << 7;
    for (int e = tid; e < 128 * 128; e += 288) {
        int i = e >> 7, j = e & 127;
        int row = m0 + i, coln = n0 + j;
        int rrow_i = (EPI == 5) ? perm_row(row) : row;
        int srow_i = (EPI == 6) ? perm_row(row) : row;
        float acc = 0.0f;
        for (int k = 0; k < K; k++)
            acc += __bfloat162float(A[(size_t)row * K + k]) *
                   __bfloat162float(B[(size_t)coln * K + k]);
        float v = acc;
        if (EPI == 2 || EPI == 3 || EPI == 6) v += bias[coln];
        if (EPI == 2) {
            ((__nv_bfloat16*)C)[(size_t)srow_i * N + coln] = __float2bfloat16(gelu_tanh(v));
        } else {
            if (EPI >= 3) v += res[(size_t)rrow_i * N + coln];
            C[(size_t)srow_i * N + coln] = v;
        }
    }
#endif
}

// ---------------- windowed attention: fp32 qkv in, bf16 o out ----------------
__global__ __launch_bounds__(224) void attn_kernel(const float* __restrict__ qkv,
                                                   const float* __restrict__ rpb,
                                                   __nv_bfloat16* __restrict__ o) {
    __shared__ float sQ[NT * 32];
    __shared__ float sK[NT * 36];
    __shared__ float sV[NT * 32];
    __shared__ float sS[NT * 52];
    __shared__ float sB[169];

    int w = blockIdx.x / HEADS, hh = blockIdx.x % HEADS;
    int tid = threadIdx.x, warp = tid >> 5, lane = tid & 31;
    const float* basep = qkv + (size_t)(w * NT) * (3 * CC) + hh * HD;

    for (int i = tid; i < NT * 8; i += 224) {
        int t = i >> 3, d4 = i & 7;
        const float4* p = (const float4*)(basep + (size_t)t * (3 * CC));
        *(float4*)&sQ[t * 32 + d4 * 4] = p[d4];
        *(float4*)&sK[t * 36 + d4 * 4] = p[96 + d4];
        *(float4*)&sV[t * 32 + d4 * 4] = p[192 + d4];
    }
    for (int i = tid; i < 169; i += 224) sB[i] = rpb[i * HEADS + hh];
    __syncthreads();

    const float scale = 0.17677669529663687f;
    int q0 = warp * 7;
    int k1 = lane, k2 = lane + 32;

    {
        float a0[7], a1[7];
        #pragma unroll
        for (int i = 0; i < 7; i++) { a0[i] = 0.0f; a1[i] = 0.0f; }
        #pragma unroll
        for (int d4 = 0; d4 < 8; d4++) {
            float4 kv1 = *(const float4*)&sK[k1 * 36 + d4 * 4];
            float4 kv2 = (k2 < NT) ? *(const float4*)&sK[k2 * 36 + d4 * 4]
                                   : make_float4(0.f, 0.f, 0.f, 0.f);
            #pragma unroll
            for (int i = 0; i < 7; i++) {
                float4 qv = *(const float4*)&sQ[(q0 + i) * 32 + d4 * 4];
                a0[i] += qv.x * kv1.x + qv.y * kv1.y + qv.z * kv1.z + qv.w * kv1.w;
                a1[i] += qv.x * kv2.x + qv.y * kv2.y + qv.z * kv2.z + qv.w * kv2.w;
            }
        }
        int k1y = k1 / WS, k1x = k1 - k1y * WS;
        int k2y = k2 / WS, k2x = k2 - k2y * WS;
        #pragma unroll
        for (int i = 0; i < 7; i++) {
            int q = q0 + i;
            int qy = q / WS, qx = q - qy * WS;
            sS[q * 52 + k1] = a0[i] * scale + sB[(qy - k1y + 6) * 13 + (qx - k1x + 6)];
            if (k2 < NT)
                sS[q * 52 + k2] = a1[i] * scale + sB[(qy - k2y + 6) * 13 + (qx - k2x + 6)];
        }
    }
    __syncthreads();

    #pragma unroll
    for (int i = 0; i < 7; i++) {
        int row = q0 + i;
        float v0 = sS[row * 52 + lane];
        float v1 = (lane < 17) ? sS[row * 52 + 32 + lane] : -INFINITY;
        float m = fmaxf(v0, v1);
        #pragma unroll
        for (int ofs = 16; ofs; ofs >>= 1) m = fmaxf(m, __shfl_xor_sync(0xffffffffu, m, ofs));
        float e0 = __expf(v0 - m);
        float e1 = (lane < 17) ? __expf(v1 - m) : 0.0f;
        float sum = e0 + e1;
        #pragma unroll
        for (int ofs = 16; ofs; ofs >>= 1) sum += __shfl_xor_sync(0xffffffffu, sum, ofs);
        float inv = 1.0f / sum;
        sS[row * 52 + lane] = e0 * inv;
        if (lane < 17) sS[row * 52 + 32 + lane] = e1 * inv;
    }
    __syncthreads();

    {
        float outv[7];
        #pragma unroll
        for (int i = 0; i < 7; i++) outv[i] = 0.0f;
        #pragma unroll
        for (int k4 = 0; k4 < 48; k4 += 4) {
            float vk0 = sV[(k4 + 0) * 32 + lane];
            float vk1 = sV[(k4 + 1) * 32 + lane];
            float vk2 = sV[(k4 + 2) * 32 + lane];
            float vk3 = sV[(k4 + 3) * 32 + lane];
            #pragma unroll
            for (int i = 0; i < 7; i++) {
                float4 sv = *(const float4*)&sS[(q0 + i) * 52 + k4];
                outv[i] += sv.x * vk0 + sv.y * vk1 + sv.z * vk2 + sv.w * vk3;
            }
        }
        float vkl = sV[48 * 32 + lane];
        #pragma unroll
        for (int i = 0; i < 7; i++) outv[i] += sS[(q0 + i) * 52 + 48] * vkl;
        #pragma unroll
        for (int i = 0; i < 7; i++)
            o[(size_t)(w * NT + q0 + i) * CC + hh * HD + lane] = __float2bfloat16(outv[i]);
    }
}

// ---------------- launch ----------------
extern "C" void kernel_launch(void* const* d_in, const int* in_sizes, int n_in,
                              void* d_out, int out_size) {
    const float* x      = (const float*)d_in[0];
    const float* ln1_s  = (const float*)d_in[1];
    const float* ln1_b  = (const float*)d_in[2];
    const float* qkv_w  = (const float*)d_in[3];
    const float* rpb    = (const float*)d_in[4];
    const float* proj_w = (const float*)d_in[5];
    const float* ln2_s  = (const float*)d_in[6];
    const float* ln2_b  = (const float*)d_in[7];
    const float* mlp_w1 = (const float*)d_in[8];
    const float* mlp_b1 = (const float*)d_in[9];
    const float* mlp_w2 = (const float*)d_in[10];
    const float* mlp_b2 = (const float*)d_in[11];
    float* out = (float*)d_out;

    float *xw, *qkv;
    __nv_bfloat16 *h, *o, *hidden, *wT;
    cudaGetSymbolAddress((void**)&xw, g_xw);
    cudaGetSymbolAddress((void**)&h, g_h);
    cudaGetSymbolAddress((void**)&qkv, g_qkv);
    cudaGetSymbolAddress((void**)&o, g_o);
    cudaGetSymbolAddress((void**)&hidden, g_hidden);
    cudaGetSymbolAddress((void**)&wT, g_wT);

    const int SMEM_SZ = 1024 + NSTAGE * STAGE_BYTES + 128;
    cudaFuncSetAttribute(tc_gemm<0>, cudaFuncAttributeMaxDynamicSharedMemorySize, SMEM_SZ);
    cudaFuncSetAttribute(tc_gemm<2>, cudaFuncAttributeMaxDynamicSharedMemorySize, SMEM_SZ);
    cudaFuncSetAttribute(tc_gemm<3>, cudaFuncAttributeMaxDynamicSharedMemorySize, SMEM_SZ);
    cudaFuncSetAttribute(tc_gemm<4>, cudaFuncAttributeMaxDynamicSharedMemorySize, SMEM_SZ);
    cudaFuncSetAttribute(tc_gemm<5>, cudaFuncAttributeMaxDynamicSharedMemorySize, SMEM_SZ);
    cudaFuncSetAttribute(tc_gemm<6>, cudaFuncAttributeMaxDynamicSharedMemorySize, SMEM_SZ);

    transpose_all<<<dim3(1728, 2), dim3(32, 8)>>>(qkv_w, proj_w, mlp_w1, mlp_w2, wT);

    const int MT = MROWS / 128;  // 392
    for (int l = 0; l < 2; l++) {
        __nv_bfloat16* wl = wT + (size_t)l * WT_LAYER;
        if (l == 0)
            ln_kernel<1><<<MROWS / 8, 256>>>(x, ln1_s, ln1_b, h);
        else
            ln_kernel<0><<<MROWS / 8, 256>>>(xw, ln1_s + CC, ln1_b + CC, h);
        tc_gemm<0><<<dim3(9, MT), 288, SMEM_SZ>>>(h, wl + OFF_QKV, nullptr, nullptr, qkv, 384, 1152);
        attn_kernel<<<NWIN * HEADS, 224>>>(qkv, rpb + (size_t)l * 169 * HEADS, o);
        if (l == 0)
            tc_gemm<5><<<dim3(3, MT), 288, SMEM_SZ>>>(o, wl + OFF_PROJ, nullptr, x, xw, 384, 384);
        else
            tc_gemm<4><<<dim3(3, MT), 288, SMEM_SZ>>>(o, wl + OFF_PROJ, nullptr, xw, xw, 384, 384);
        ln_kernel<0><<<MROWS / 8, 256>>>(xw, ln2_s + l * CC, ln2_b + l * CC, h);
        tc_gemm<2><<<dim3(12, MT), 288, SMEM_SZ>>>(h, wl + OFF_W1, mlp_b1 + (size_t)l * 1536,
                                                   nullptr, (float*)hidden, 384, 1536);
        if (l == 0)
            tc_gemm<3><<<dim3(3, MT), 288, SMEM_SZ>>>(hidden, wl + OFF_W2, mlp_b2,
                                                      xw, xw, 1536, 384);
        else
            tc_gemm<6><<<dim3(3, MT), 288, SMEM_SZ>>>(hidden, wl + OFF_W2, mlp_b2 + 384,
                                                      xw, out, 1536, 384);
    }
}

// round 17
// speedup vs baseline: 1.3858x; 1.3858x over previous
#include <cuda_runtime.h>
#include <cuda_bf16.h>
#include <math.h>
#include <stdint.h>

// ---------------- problem constants ----------------
#define CC 384
#define WS 7
#define NT 49
#define HEADS 12
#define HD 32
#define NWIN 1024
#define MROWS (NWIN * NT)   // 50176
#define C4 (CC / 4)

#if defined(__CUDA_ARCH_FEAT_SM103_ALL) || defined(__CUDA_ARCH_FEAT_SM100_ALL) || defined(__CUDA_ARCH_FEAT_SM101_ALL)
#define TC_OK 1
#else
#define TC_OK 0
#endif

// ---------------- scratch (device globals) ----------------
__device__ float g_xw[MROWS * CC];                 // residual stream (fp32)
__device__ __nv_bfloat16 g_h[MROWS * CC];          // LN output (bf16)
__device__ float g_qkv[MROWS * 3 * CC];            // qkv (fp32, feeds attention)
__device__ __nv_bfloat16 g_o[MROWS * CC];          // attention output (bf16)
__device__ __nv_bfloat16 g_hidden[MROWS * 4 * CC]; // gelu output (bf16)
#define WT_LAYER 1769472
__device__ __nv_bfloat16 g_wT[2 * WT_LAYER];       // transposed weights (bf16)

#define OFF_QKV  0
#define OFF_PROJ 442368
#define OFF_W1   589824
#define OFF_W2   1179648

// ---------------- small helpers ----------------
__device__ __forceinline__ uint32_t smem_u32(const void* p) {
    uint32_t a;
    asm("{ .reg .u64 t; cvta.to.shared.u64 t, %1; cvt.u32.u64 %0, t; }" : "=r"(a) : "l"(p));
    return a;
}
__device__ __forceinline__ void cp16(uint32_t dst, const void* src) {
    asm volatile("cp.async.cg.shared.global [%0], [%1], 16;" :: "r"(dst), "l"(src));
}
// windowed row r <-> image row perm(r)
__device__ __forceinline__ int perm_row(int r) {
    int w = r / NT, tt = r - w * NT;
    int b = w >> 6, wrem = w & 63, wy = wrem >> 3, wx = wrem & 7;
    int ty = tt / WS, tx = tt - ty * WS;
    return (b * 56 + wy * WS + ty) * 56 + wx * WS + tx;
}

// SW128 swizzle (128B rows): bits[6:4] ^= bits[9:7]
#define SWZ128(o) ((o) ^ (((o) >> 3) & 0x70))
// SW128 K-major smem descriptor: layout=2, version=1, SBO=64 (1024B atom), LBO=1
#define DESC_SW128 ((2ull << 61) | (1ull << 46) | (64ull << 32) | (1ull << 16))
// idesc kind::f16 bf16: dtype=F32(1<<4), atype=BF16(1<<7), btype=BF16(1<<10),
// N=128 (16<<17), M=128 (8<<24)
#define IDESC_BF16 0x08200490u

#define STAGE_BYTES 32768          // A 16KB + B 16KB  (K-chunk = 64 bf16 per 128B row)
#define NSTAGE 2

#if TC_OK
__device__ __forceinline__ void mbar_wait(uint32_t mb, int parity) {
    asm volatile(
        "{\n\t.reg .pred P;\n"
        "W%=:\n\t"
        "mbarrier.try_wait.parity.acquire.cta.shared::cta.b64 P, [%0], %1, 0x989680;\n\t"
        "@P bra D%=;\n\t"
        "bra W%=;\n"
        "D%=:\n\t}"
        :: "r"(mb), "r"(parity) : "memory");
}
__device__ __forceinline__ void mma_bf16_ss(uint32_t d, uint64_t a, uint64_t b,
                                            uint32_t idesc, uint32_t en) {
    asm volatile(
        "{\n\t.reg .pred p;\n\t"
        "setp.ne.u32 p, %4, 0;\n\t"
        "tcgen05.mma.cta_group::1.kind::f16 [%0], %1, %2, %3, p;\n\t}"
        :: "r"(d), "l"(a), "l"(b), "r"(idesc), "r"(en) : "memory");
}
#define LDTM_X16(r, a) \
    asm volatile("tcgen05.ld.sync.aligned.32x32b.x16.b32 " \
        "{%0,%1,%2,%3,%4,%5,%6,%7,%8,%9,%10,%11,%12,%13,%14,%15}, [%16];" \
        : "=r"((r)[0]),"=r"((r)[1]),"=r"((r)[2]),"=r"((r)[3]), \
          "=r"((r)[4]),"=r"((r)[5]),"=r"((r)[6]),"=r"((r)[7]), \
          "=r"((r)[8]),"=r"((r)[9]),"=r"((r)[10]),"=r"((r)[11]), \
          "=r"((r)[12]),"=r"((r)[13]),"=r"((r)[14]),"=r"((r)[15]) \
        : "r"(a))
#endif

// ---------------- fused weight transpose -> bf16 K-major ----------------
__global__ void transpose_all(const float* __restrict__ qkv_w,
                              const float* __restrict__ proj_w,
                              const float* __restrict__ w1,
                              const float* __restrict__ w2,
                              __nv_bfloat16* __restrict__ wT) {
    __shared__ float t[32][33];
    int id = blockIdx.x, l = blockIdx.y;
    const float* src; size_t doff; int K, N, tn;
    if (id < 432)       { src = qkv_w  + (size_t)l*384*1152; doff = OFF_QKV;  K = 384;  N = 1152; tn = 36; }
    else if (id < 576)  { id -= 432; src = proj_w + (size_t)l*384*384;  doff = OFF_PROJ; K = 384;  N = 384;  tn = 12; }
    else if (id < 1152) { id -= 576; src = w1     + (size_t)l*384*1536; doff = OFF_W1;   K = 384;  N = 1536; tn = 48; }
    else                { id -= 1152; src = w2    + (size_t)l*1536*384; doff = OFF_W2;   K = 1536; N = 384;  tn = 12; }
    __nv_bfloat16* dst = wT + (size_t)l * WT_LAYER + doff;
    int k0 = (id / tn) * 32, n0 = (id % tn) * 32;
    int tx = threadIdx.x, ty = threadIdx.y;
    #pragma unroll
    for (int i = 0; i < 32; i += 8)
        t[ty + i][tx] = src[(size_t)(k0 + ty + i) * N + n0 + tx];
    __syncthreads();
    #pragma unroll
    for (int i = 0; i < 32; i += 8)
        dst[(size_t)(n0 + ty + i) * K + k0 + tx] = __float2bfloat16(t[tx][ty + i]);
}

// ---------------- layernorm: fp32 in -> bf16 out ----------------
template <int PERM>
__global__ __launch_bounds__(256) void ln_kernel(const float* __restrict__ xin,
                                                 const float* __restrict__ sc,
                                                 const float* __restrict__ bi,
                                                 __nv_bfloat16* __restrict__ outp) {
    int warp = threadIdx.x >> 5, lane = threadIdx.x & 31;
    int row = blockIdx.x * 8 + warp;
    int srow = PERM ? perm_row(row) : row;
    const float4* xr = (const float4*)(xin + (size_t)srow * CC);
    float4 v0 = xr[lane], v1 = xr[lane + 32], v2 = xr[lane + 64];
    float s = v0.x + v0.y + v0.z + v0.w + v1.x + v1.y + v1.z + v1.w + v2.x + v2.y + v2.z + v2.w;
    float s2 = v0.x*v0.x + v0.y*v0.y + v0.z*v0.z + v0.w*v0.w
             + v1.x*v1.x + v1.y*v1.y + v1.z*v1.z + v1.w*v1.w
             + v2.x*v2.x + v2.y*v2.y + v2.z*v2.z + v2.w*v2.w;
    #pragma unroll
    for (int o = 16; o; o >>= 1) {
        s  += __shfl_xor_sync(0xffffffffu, s, o);
        s2 += __shfl_xor_sync(0xffffffffu, s2, o);
    }
    float mu = s * (1.0f / CC);
    float var = s2 * (1.0f / CC) - mu * mu;
    float rstd = rsqrtf(var + 1e-6f);
    const float4* s4 = (const float4*)sc;
    const float4* b4 = (const float4*)bi;
    __nv_bfloat16* orow = outp + (size_t)row * CC;
    #pragma unroll
    for (int c = 0; c < 3; c++) {
        float4 v = c == 0 ? v0 : (c == 1 ? v1 : v2);
        float4 g = s4[lane + c * 32], bb = b4[lane + c * 32];
        float rx = (v.x - mu) * rstd * g.x + bb.x;
        float ry = (v.y - mu) * rstd * g.y + bb.y;
        float rz = (v.z - mu) * rstd * g.z + bb.z;
        float rw = (v.w - mu) * rstd * g.w + bb.w;
        __nv_bfloat162 p0 = __floats2bfloat162_rn(rx, ry);
        __nv_bfloat162 p1 = __floats2bfloat162_rn(rz, rw);
        uint2 pk;
        pk.x = *(uint32_t*)&p0;
        pk.y = *(uint32_t*)&p1;
        *(uint2*)(orow + (lane + c * 32) * 4) = pk;
    }
}

// ---------------- gelu ----------------
__device__ __forceinline__ float gelu_tanh(float x) {
    float x3 = x * x * x;
    return 0.5f * x * (1.0f + tanhf(0.7978845608028654f * (x + 0.044715f * x3)));
}

// ---------------- GEMM: C[M,N] = A[M,K] * B[N,K]^T ; bf16 in, fp32 acc ----------------
// CTA tile 128x128, K-stage = 64 bf16 (SW128 128B rows): 2 stages = 64KB -> 3 CTA/SM.
// Per the measured law (time ~ waves x stages), K64 halves stage count; 4 MMAs
// (K16 each) per full-wait/commit iteration.
// 288 threads: warps 0-7 load (256 threads x 8 chunks), warp 8 lane 0 issues MMAs.
// EPI: 0 qkv fp32 | 2 gelu+bias->bf16 | 3 acc+bias+res | 4 acc+res
//      5 acc+res(perm rows) | 6 acc+bias+res store-permuted
template <int EPI>
__global__ __launch_bounds__(288, 3) void tc_gemm(const __nv_bfloat16* __restrict__ A,
                                                  const __nv_bfloat16* __restrict__ B,
                                                  const float* __restrict__ bias,
                                                  const float* __restrict__ res,
                                                  float* __restrict__ C,
                                                  int K, int N) {
    extern __shared__ char smem[];
#if TC_OK
    uint32_t raw = smem_u32(smem);
    uint32_t base = (raw + 1023) & ~1023u;
    uint32_t ctrl = base + NSTAGE * STAGE_BYTES;
    uint32_t fullb[2] = {ctrl, ctrl + 8};
    uint32_t doneb[2] = {ctrl + 16, ctrl + 24};
    uint32_t tptr = ctrl + 32;
    int tid = threadIdx.x, wid = tid >> 5, lane = tid & 31;
    int m0 = blockIdx.y << 7;
    int n0 = blockIdx.x << 7;
    int S = K >> 6;   // K stages of 64 (6 or 24)

    auto load_stage = [&](int s) {   // tid < 256 only
        int b = s & 1;
        uint32_t st = base + b * STAGE_BYTES;
        int k0 = s << 6;
        #pragma unroll
        for (int i = 0; i < 8; i++) {
            int g = (i << 8) + tid;            // 0..2047 16B-chunks
            int tile = g >> 10;                // 0 = A, 1 = B
            int w = g & 1023;
            int row = w >> 3;
            int cb  = (w & 7) << 4;            // byte col in 128B row
            uint32_t dst = st + (tile << 14) + SWZ128(row * 128 + cb);
            const __nv_bfloat16* src = (tile == 0)
                ? A + (size_t)(m0 + row) * K + k0 + (cb >> 1)
                : B + (size_t)(n0 + row) * K + k0 + (cb >> 1);
            cp16(dst, src);
        }
        asm volatile("cp.async.mbarrier.arrive.noinc.shared::cta.b64 [%0];"
                     :: "r"(fullb[b]) : "memory");
    };

    if (wid == 0) {
        asm volatile("tcgen05.alloc.cta_group::1.sync.aligned.shared::cta.b32 [%0], %1;"
                     :: "r"(tptr), "r"(128) : "memory");
        asm volatile("tcgen05.relinquish_alloc_permit.cta_group::1.sync.aligned;");
    }
    if (tid == 0) {
        #pragma unroll
        for (int i = 0; i < 2; i++) {
            asm volatile("mbarrier.init.shared.b64 [%0], 256;" :: "r"(fullb[i]) : "memory");
            asm volatile("mbarrier.init.shared.b64 [%0], 1;"   :: "r"(doneb[i]) : "memory");
        }
    }
    __syncthreads();
    uint32_t tmem;
    asm volatile("ld.shared.b32 %0, [%1];" : "=r"(tmem) : "r"(tptr));

    if (tid < 256) {
        load_stage(0);
        load_stage(1);
    }

    if (wid == 8) {
        // ---- MMA issuer: gated only by full[b] ----
        if (lane == 0) {
            int fph[2] = {0, 0};
            for (int s = 0; s < S; s++) {
                int b = s & 1;
                mbar_wait(fullb[b], fph[b]); fph[b] ^= 1;
                asm volatile("fence.proxy.async.shared::cta;" ::: "memory");
                uint32_t st = base + b * STAGE_BYTES;
                uint64_t ad = DESC_SW128 | ((uint64_t)(st >> 4) & 0x3FFF);
                uint64_t bd = DESC_SW128 | ((uint64_t)((st + 16384) >> 4) & 0x3FFF);
                #pragma unroll
                for (int ks = 0; ks < 4; ks++)   // 4 x K=16 bf16 MMAs per stage
                    mma_bf16_ss(tmem, ad + 2 * ks, bd + 2 * ks,
                                IDESC_BF16, (s | ks) != 0);
                asm volatile("tcgen05.commit.cta_group::1.mbarrier::arrive::one.shared::cluster.b64 [%0];"
                             :: "r"(doneb[b]) : "memory");
            }
        }
    } else {
        // ---- loaders: gated only by done[b] (buffer recycling) ----
        int dph[2] = {0, 0};
        for (int s = 2; s < S; s++) {
            int b = s & 1;
            mbar_wait(doneb[b], dph[b]); dph[b] ^= 1;
            load_stage(s);
        }
        int bl = (S - 1) & 1;
        mbar_wait(doneb[bl], dph[bl]);
    }
    __syncthreads();

    asm volatile("tcgen05.fence::after_thread_sync;" ::: "memory");
    if (wid < 8) {
        int row = m0 + ((wid & 3) << 5) + lane;
        int rrow_i = (EPI == 5) ? perm_row(row) : row;   // residual source row
        int srow_i = (EPI == 6) ? perm_row(row) : row;   // store destination row
        int colbase = (wid >> 2) << 6;
        uint32_t toff = tmem + ((uint32_t)(wid & 3) << 21);
        #pragma unroll
        for (int g = 0; g < 4; g++) {
            int col = colbase + g * 16;
            uint32_t r[16];
            LDTM_X16(r, toff + col);
            asm volatile("tcgen05.wait::ld.sync.aligned;" ::: "memory");
            float* crow = C + (size_t)srow_i * N + n0 + col;
            __nv_bfloat16* crow16 = (__nv_bfloat16*)C + (size_t)srow_i * N + n0 + col;
            const float4* rrow = (EPI >= 3)
                ? (const float4*)(res + (size_t)rrow_i * N + n0 + col) : nullptr;
            const float4* b4 = (EPI == 2 || EPI == 3 || EPI == 6)
                ? (const float4*)(bias + n0 + col) : nullptr;
            #pragma unroll
            for (int j = 0; j < 16; j += 4) {
                float4 v;
                v.x = __uint_as_float(r[j + 0]);
                v.y = __uint_as_float(r[j + 1]);
                v.z = __uint_as_float(r[j + 2]);
                v.w = __uint_as_float(r[j + 3]);
                if (EPI == 2 || EPI == 3 || EPI == 6) {
                    float4 bb = b4[j >> 2];
                    v.x += bb.x; v.y += bb.y; v.z += bb.z; v.w += bb.w;
                }
                if (EPI == 2) {
                    v.x = gelu_tanh(v.x); v.y = gelu_tanh(v.y);
                    v.z = gelu_tanh(v.z); v.w = gelu_tanh(v.w);
                    __nv_bfloat162 p0 = __floats2bfloat162_rn(v.x, v.y);
                    __nv_bfloat162 p1 = __floats2bfloat162_rn(v.z, v.w);
                    *(__nv_bfloat162*)(crow16 + j)     = p0;
                    *(__nv_bfloat162*)(crow16 + j + 2) = p1;
                } else {
                    if (EPI >= 3) {
                        float4 rr = rrow[j >> 2];
                        v.x += rr.x; v.y += rr.y; v.z += rr.z; v.w += rr.w;
                    }
                    *(float4*)(crow + j) = v;
                }
            }
        }
    }
    __syncthreads();
    if (wid == 0)
        asm volatile("tcgen05.dealloc.cta_group::1.sync.aligned.b32 %0, %1;"
                     :: "r"(tmem), "r"(128));
#else
    // ---------- SIMT fallback (plain sm_103 target; never selected at runtime) ----------
    (void)smem;
    int tid = threadIdx.x;
    int m0 = blockIdx.y << 7;
    int n0 = blockIdx.x << 7;
    for (int e = tid; e < 128 * 128; e += 288) {
        int i = e >> 7, j = e & 127;
        int row = m0 + i, coln = n0 + j;
        int rrow_i = (EPI == 5) ? perm_row(row) : row;
        int srow_i = (EPI == 6) ? perm_row(row) : row;
        float acc = 0.0f;
        for (int k = 0; k < K; k++)
            acc += __bfloat162float(A[(size_t)row * K + k]) *
                   __bfloat162float(B[(size_t)coln * K + k]);
        float v = acc;
        if (EPI == 2 || EPI == 3 || EPI == 6) v += bias[coln];
        if (EPI == 2) {
            ((__nv_bfloat16*)C)[(size_t)srow_i * N + coln] = __float2bfloat16(gelu_tanh(v));
        } else {
            if (EPI >= 3) v += res[(size_t)rrow_i * N + coln];
            C[(size_t)srow_i * N + coln] = v;
        }
    }
#endif
}

// ---------------- windowed attention: fp32 qkv in, bf16 o out ----------------
__global__ __launch_bounds__(224) void attn_kernel(const float* __restrict__ qkv,
                                                   const float* __restrict__ rpb,
                                                   __nv_bfloat16* __restrict__ o) {
    __shared__ float sQ[NT * 32];
    __shared__ float sK[NT * 36];
    __shared__ float sV[NT * 32];
    __shared__ float sS[NT * 52];
    __shared__ float sB[169];

    int w = blockIdx.x / HEADS, hh = blockIdx.x % HEADS;
    int tid = threadIdx.x, warp = tid >> 5, lane = tid & 31;
    const float* basep = qkv + (size_t)(w * NT) * (3 * CC) + hh * HD;

    for (int i = tid; i < NT * 8; i += 224) {
        int t = i >> 3, d4 = i & 7;
        const float4* p = (const float4*)(basep + (size_t)t * (3 * CC));
        *(float4*)&sQ[t * 32 + d4 * 4] = p[d4];
        *(float4*)&sK[t * 36 + d4 * 4] = p[96 + d4];
        *(float4*)&sV[t * 32 + d4 * 4] = p[192 + d4];
    }
    for (int i = tid; i < 169; i += 224) sB[i] = rpb[i * HEADS + hh];
    __syncthreads();

    const float scale = 0.17677669529663687f;
    int q0 = warp * 7;
    int k1 = lane, k2 = lane + 32;

    {
        float a0[7], a1[7];
        #pragma unroll
        for (int i = 0; i < 7; i++) { a0[i] = 0.0f; a1[i] = 0.0f; }
        #pragma unroll
        for (int d4 = 0; d4 < 8; d4++) {
            float4 kv1 = *(const float4*)&sK[k1 * 36 + d4 * 4];
            float4 kv2 = (k2 < NT) ? *(const float4*)&sK[k2 * 36 + d4 * 4]
                                   : make_float4(0.f, 0.f, 0.f, 0.f);
            #pragma unroll
            for (int i = 0; i < 7; i++) {
                float4 qv = *(const float4*)&sQ[(q0 + i) * 32 + d4 * 4];
                a0[i] += qv.x * kv1.x + qv.y * kv1.y + qv.z * kv1.z + qv.w * kv1.w;
                a1[i] += qv.x * kv2.x + qv.y * kv2.y + qv.z * kv2.z + qv.w * kv2.w;
            }
        }
        int k1y = k1 / WS, k1x = k1 - k1y * WS;
        int k2y = k2 / WS, k2x = k2 - k2y * WS;
        #pragma unroll
        for (int i = 0; i < 7; i++) {
            int q = q0 + i;
            int qy = q / WS, qx = q - qy * WS;
            sS[q * 52 + k1] = a0[i] * scale + sB[(qy - k1y + 6) * 13 + (qx - k1x + 6)];
            if (k2 < NT)
                sS[q * 52 + k2] = a1[i] * scale + sB[(qy - k2y + 6) * 13 + (qx - k2x + 6)];
        }
    }
    __syncthreads();

    #pragma unroll
    for (int i = 0; i < 7; i++) {
        int row = q0 + i;
        float v0 = sS[row * 52 + lane];
        float v1 = (lane < 17) ? sS[row * 52 + 32 + lane] : -INFINITY;
        float m = fmaxf(v0, v1);
        #pragma unroll
        for (int ofs = 16; ofs; ofs >>= 1) m = fmaxf(m, __shfl_xor_sync(0xffffffffu, m, ofs));
        float e0 = __expf(v0 - m);
        float e1 = (lane < 17) ? __expf(v1 - m) : 0.0f;
        float sum = e0 + e1;
        #pragma unroll
        for (int ofs = 16; ofs; ofs >>= 1) sum += __shfl_xor_sync(0xffffffffu, sum, ofs);
        float inv = 1.0f / sum;
        sS[row * 52 + lane] = e0 * inv;
        if (lane < 17) sS[row * 52 + 32 + lane] = e1 * inv;
    }
    __syncthreads();

    {
        float outv[7];
        #pragma unroll
        for (int i = 0; i < 7; i++) outv[i] = 0.0f;
        #pragma unroll
        for (int k4 = 0; k4 < 48; k4 += 4) {
            float vk0 = sV[(k4 + 0) * 32 + lane];
            float vk1 = sV[(k4 + 1) * 32 + lane];
            float vk2 = sV[(k4 + 2) * 32 + lane];
            float vk3 = sV[(k4 + 3) * 32 + lane];
            #pragma unroll
            for (int i = 0; i < 7; i++) {
                float4 sv = *(const float4*)&sS[(q0 + i) * 52 + k4];
                outv[i] += sv.x * vk0 + sv.y * vk1 + sv.z * vk2 + sv.w * vk3;
            }
        }
        float vkl = sV[48 * 32 + lane];
        #pragma unroll
        for (int i = 0; i < 7; i++) outv[i] += sS[(q0 + i) * 52 + 48] * vkl;
        #pragma unroll
        for (int i = 0; i < 7; i++)
            o[(size_t)(w * NT + q0 + i) * CC + hh * HD + lane] = __float2bfloat16(outv[i]);
    }
}

// ---------------- launch ----------------
extern "C" void kernel_launch(void* const* d_in, const int* in_sizes, int n_in,
                              void* d_out, int out_size) {
    const float* x      = (const float*)d_in[0];
    const float* ln1_s  = (const float*)d_in[1];
    const float* ln1_b  = (const float*)d_in[2];
    const float* qkv_w  = (const float*)d_in[3];
    const float* rpb    = (const float*)d_in[4];
    const float* proj_w = (const float*)d_in[5];
    const float* ln2_s  = (const float*)d_in[6];
    const float* ln2_b  = (const float*)d_in[7];
    const float* mlp_w1 = (const float*)d_in[8];
    const float* mlp_b1 = (const float*)d_in[9];
    const float* mlp_w2 = (const float*)d_in[10];
    const float* mlp_b2 = (const float*)d_in[11];
    float* out = (float*)d_out;

    float *xw, *qkv;
    __nv_bfloat16 *h, *o, *hidden, *wT;
    cudaGetSymbolAddress((void**)&xw, g_xw);
    cudaGetSymbolAddress((void**)&h, g_h);
    cudaGetSymbolAddress((void**)&qkv, g_qkv);
    cudaGetSymbolAddress((void**)&o, g_o);
    cudaGetSymbolAddress((void**)&hidden, g_hidden);
    cudaGetSymbolAddress((void**)&wT, g_wT);

    const int SMEM_SZ = 1024 + NSTAGE * STAGE_BYTES + 64;
    cudaFuncSetAttribute(tc_gemm<0>, cudaFuncAttributeMaxDynamicSharedMemorySize, SMEM_SZ);
    cudaFuncSetAttribute(tc_gemm<2>, cudaFuncAttributeMaxDynamicSharedMemorySize, SMEM_SZ);
    cudaFuncSetAttribute(tc_gemm<3>, cudaFuncAttributeMaxDynamicSharedMemorySize, SMEM_SZ);
    cudaFuncSetAttribute(tc_gemm<4>, cudaFuncAttributeMaxDynamicSharedMemorySize, SMEM_SZ);
    cudaFuncSetAttribute(tc_gemm<5>, cudaFuncAttributeMaxDynamicSharedMemorySize, SMEM_SZ);
    cudaFuncSetAttribute(tc_gemm<6>, cudaFuncAttributeMaxDynamicSharedMemorySize, SMEM_SZ);

    transpose_all<<<dim3(1728, 2), dim3(32, 8)>>>(qkv_w, proj_w, mlp_w1, mlp_w2, wT);

    const int MT = MROWS / 128;  // 392
    for (int l = 0; l < 2; l++) {
        __nv_bfloat16* wl = wT + (size_t)l * WT_LAYER;
        if (l == 0)
            ln_kernel<1><<<MROWS / 8, 256>>>(x, ln1_s, ln1_b, h);
        else
            ln_kernel<0><<<MROWS / 8, 256>>>(xw, ln1_s + CC, ln1_b + CC, h);
        tc_gemm<0><<<dim3(9, MT), 288, SMEM_SZ>>>(h, wl + OFF_QKV, nullptr, nullptr, qkv, 384, 1152);
        attn_kernel<<<NWIN * HEADS, 224>>>(qkv, rpb + (size_t)l * 169 * HEADS, o);
        if (l == 0)
            tc_gemm<5><<<dim3(3, MT), 288, SMEM_SZ>>>(o, wl + OFF_PROJ, nullptr, x, xw, 384, 384);
        else
            tc_gemm<4><<<dim3(3, MT), 288, SMEM_SZ>>>(o, wl + OFF_PROJ, nullptr, xw, xw, 384, 384);
        ln_kernel<0><<<MROWS / 8, 256>>>(xw, ln2_s + l * CC, ln2_b + l * CC, h);
        tc_gemm<2><<<dim3(12, MT), 288, SMEM_SZ>>>(h, wl + OFF_W1, mlp_b1 + (size_t)l * 1536,
                                                   nullptr, (float*)hidden, 384, 1536);
        if (l == 0)
            tc_gemm<3><<<dim3(3, MT), 288, SMEM_SZ>>>(hidden, wl + OFF_W2, mlp_b2,
                                                      xw, xw, 1536, 384);
        else
            tc_gemm<6><<<dim3(3, MT), 288, SMEM_SZ>>>(hidden, wl + OFF_W2, mlp_b2 + 384,
                                                      xw, out, 1536, 384);
    }
}